// round 9
// baseline (speedup 1.0000x reference)
#include <cuda_runtime.h>
#include <cuda_fp16.h>
#include <cstdint>

// Problem (fixed): B=4,N=2048,Fin=128,H=4,Fout=32.
// Identity: softmax(scores,m).sum(m)==1  =>  out = (1+self_weight)*(x @ W).
// adj, att are dead inputs.
//
// R9: two-kernel scheme.
//  Kernel 1 (prep): x -> fp16 (xg), W -> exact fp16 hi/lo split (whg/wlg),
//                   all in __device__ global scratch.
//  Kernel 2 (main): conversion-free HMMA GEMM. Staging via cp.async with a
//                   2-stage K pipeline (k0-63 / k64-127): stage-1 copy
//                   overlaps stage-0 MMA. Tiling = R8 (TM=64,TN=64,grid 256,
//                   occ 2), math identical to R8: out ~= xh*(wh+wl).

#define MDIM 8192
#define KDIM 128
#define NDIM 128
#define TM 64
#define TN 64
#define ASTRIDE 272   // A smem row: 128 fp16 = 256B data + 16 pad
#define BSTRIDE 144   // B smem row: 64 fp16 = 128B data + 16 pad

#define SMEM_A  0
#define SMEM_BH (SMEM_A + TM * ASTRIDE)         // 17408
#define SMEM_BL (SMEM_BH + KDIM * BSTRIDE)      // 35840
#define SMEM_TOTAL (SMEM_BL + KDIM * BSTRIDE)   // 54272

// ---- device global scratch (pre-converted operands) ----
__device__ __align__(16) __half xg[MDIM * KDIM];     // 2 MB
__device__ __align__(16) __half whg[KDIM * NDIM];    // 32 KB
__device__ __align__(16) __half wlg[KDIM * NDIM];    // 32 KB

__device__ __forceinline__ uint32_t smem_u32(const void* p) {
    uint32_t a;
    asm("{ .reg .u64 t; cvta.to.shared.u64 t, %1; cvt.u32.u64 %0, t; }"
        : "=r"(a) : "l"(p));
    return a;
}

__device__ __forceinline__ void cp16(uint32_t smem_dst, const void* gsrc) {
    asm volatile("cp.async.cg.shared.global [%0], [%1], 16;"
                 :: "r"(smem_dst), "l"(__cvta_generic_to_global(gsrc))
                 : "memory");
}
__device__ __forceinline__ void cp_commit() {
    asm volatile("cp.async.commit_group;" ::: "memory");
}
template <int N>
__device__ __forceinline__ void cp_wait() {
    asm volatile("cp.async.wait_group %0;" :: "n"(N) : "memory");
}

__device__ __forceinline__ void ldsm4(uint32_t r[4], uint32_t addr) {
    asm volatile("ldmatrix.sync.aligned.m8n8.x4.shared.b16 {%0,%1,%2,%3}, [%4];"
                 : "=r"(r[0]), "=r"(r[1]), "=r"(r[2]), "=r"(r[3]) : "r"(addr));
}
__device__ __forceinline__ void ldsm4t(uint32_t r[4], uint32_t addr) {
    asm volatile("ldmatrix.sync.aligned.m8n8.x4.trans.shared.b16 {%0,%1,%2,%3}, [%4];"
                 : "=r"(r[0]), "=r"(r[1]), "=r"(r[2]), "=r"(r[3]) : "r"(addr));
}

__device__ __forceinline__ void mma_f16(float c[4], const uint32_t a[4],
                                        uint32_t b0, uint32_t b1) {
    asm volatile(
        "mma.sync.aligned.m16n8k16.row.col.f32.f16.f16.f32 "
        "{%0,%1,%2,%3}, {%4,%5,%6,%7}, {%8,%9}, {%0,%1,%2,%3};"
        : "+f"(c[0]), "+f"(c[1]), "+f"(c[2]), "+f"(c[3])
        : "r"(a[0]), "r"(a[1]), "r"(a[2]), "r"(a[3]), "r"(b0), "r"(b1));
}

__device__ __forceinline__ uint32_t h2_pack(float a, float b) {
    __half2 h = __float22half2_rn(make_float2(a, b));
    return *reinterpret_cast<uint32_t*>(&h);
}

// ============================ prep kernel ============================
// blocks [0, 1024): x -> fp16        (262144 float4 total, 1 per thread)
// blocks [1024, 1040): W -> hi/lo    (4096 float4 total, 1 per thread)
__global__ __launch_bounds__(256)
void prep_kernel(const float* __restrict__ x, const float* __restrict__ W) {
    const int bid = blockIdx.x;
    const int tid = threadIdx.x;
    if (bid < 1024) {
        int idx = bid * 256 + tid;                 // float4 index
        float4 f = *(const float4*)&x[(size_t)idx * 4];
        uint2 h;
        h.x = h2_pack(f.x, f.y);
        h.y = h2_pack(f.z, f.w);
        *(uint2*)&xg[(size_t)idx * 4] = h;
    } else {
        int idx = (bid - 1024) * 256 + tid;        // float4 index, < 4096
        float4 f = *(const float4*)&W[(size_t)idx * 4];
        __half2 h01 = __float22half2_rn(make_float2(f.x, f.y));
        __half2 h23 = __float22half2_rn(make_float2(f.z, f.w));
        uint2 hp, lp;
        hp.x = *reinterpret_cast<uint32_t*>(&h01);
        hp.y = *reinterpret_cast<uint32_t*>(&h23);
        lp.x = h2_pack(f.x - __half2float(h01.x), f.y - __half2float(h01.y));
        lp.y = h2_pack(f.z - __half2float(h23.x), f.w - __half2float(h23.y));
        *(uint2*)&whg[(size_t)idx * 4] = hp;
        *(uint2*)&wlg[(size_t)idx * 4] = lp;
    }
}

// ============================ main kernel ============================
__global__ __launch_bounds__(256, 2)
void gat_hmma_kernel(const float* __restrict__ self_weight,
                     float* __restrict__ out) {
    extern __shared__ char smem[];
    const uint32_t sbase = smem_u32(smem);
    const int tid = threadIdx.x;
    const int wid = tid >> 5;
    const int lid = tid & 31;

    const int bcol = blockIdx.x & 1;
    const int brow = blockIdx.x >> 1;
    const int row0 = brow * TM;
    const int col0 = bcol * TN;

    const float s = 1.0f + self_weight[0];

    // ---- cp.async staging: 2 K-stages (k 0-63, k 64-127) ----
    // per stage per thread: A 2 chunks + BH 2 + BL 2  (16B each)
    #pragma unroll
    for (int st = 0; st < 2; st++) {
        #pragma unroll
        for (int r = 0; r < 2; r++) {
            int c   = tid + r * 256;       // 0..511
            int row = c >> 3;              // 0..63
            int j   = (c & 7) + 8 * st;    // 16B chunk within 256B row
            cp16(sbase + SMEM_A + row * ASTRIDE + j * 16,
                 &xg[(size_t)(row0 + row) * KDIM + j * 8]);
        }
        #pragma unroll
        for (int r = 0; r < 2; r++) {
            int c = tid + r * 256;
            int k = 64 * st + (c >> 3);    // k row
            int j = c & 7;                 // 16B chunk within 128B half-row
            cp16(sbase + SMEM_BH + k * BSTRIDE + j * 16,
                 &whg[(size_t)k * NDIM + col0 + j * 8]);
            cp16(sbase + SMEM_BL + k * BSTRIDE + j * 16,
                 &wlg[(size_t)k * NDIM + col0 + j * 8]);
        }
        cp_commit();
    }

    // ---- fragment addressing (same as R8) ----
    const int wm = (wid >> 1) * 16;     // 0,16,32,48
    const int wn = (wid & 1) * 32;      // 0,32

    float t0[4][4], t1[4][4];
    #pragma unroll
    for (int j = 0; j < 4; j++)
        #pragma unroll
        for (int e = 0; e < 4; e++) { t0[j][e] = 0.f; t1[j][e] = 0.f; }

    const uint32_t aAddr = sbase + SMEM_A
        + (wm + (lid & 15)) * ASTRIDE + 16 * (lid >> 4);
    uint32_t bAddr[2];
    #pragma unroll
    for (int p = 0; p < 2; p++)
        bAddr[p] = sbase + SMEM_BH
            + (8 * ((lid >> 3) & 1) + (lid & 7)) * BSTRIDE
            + (wn + 16 * p + 8 * (lid >> 4)) * 2;

    const uint32_t dBL = SMEM_BL - SMEM_BH;

    // ---- stage 0 compute (k-steps 0-3) ----
    cp_wait<1>();
    __syncthreads();

    #pragma unroll
    for (int ks = 0; ks < 4; ks++) {
        const uint32_t ako = ks * 32;
        const uint32_t bko = ks * 16 * BSTRIDE;
        uint32_t ah[4];
        ldsm4(ah, aAddr + ako);
        uint32_t bh[2][4], bl[2][4];
        #pragma unroll
        for (int p = 0; p < 2; p++) {
            ldsm4t(bh[p], bAddr[p] + bko);
            ldsm4t(bl[p], bAddr[p] + bko + dBL);
        }
        #pragma unroll
        for (int nt = 0; nt < 4; nt++) {
            const int p = nt >> 1, q = (nt & 1) * 2;
            mma_f16(t0[nt], ah, bh[p][q], bh[p][q + 1]);
            mma_f16(t1[nt], ah, bl[p][q], bl[p][q + 1]);
        }
    }

    // ---- stage 1 compute (k-steps 4-7) ----
    cp_wait<0>();
    __syncthreads();

    #pragma unroll
    for (int ks = 4; ks < 8; ks++) {
        const uint32_t ako = ks * 32;
        const uint32_t bko = ks * 16 * BSTRIDE;
        uint32_t ah[4];
        ldsm4(ah, aAddr + ako);
        uint32_t bh[2][4], bl[2][4];
        #pragma unroll
        for (int p = 0; p < 2; p++) {
            ldsm4t(bh[p], bAddr[p] + bko);
            ldsm4t(bl[p], bAddr[p] + bko + dBL);
        }
        #pragma unroll
        for (int nt = 0; nt < 4; nt++) {
            const int p = nt >> 1, q = (nt & 1) * 2;
            mma_f16(t0[nt], ah, bh[p][q], bh[p][q + 1]);
            mma_f16(t1[nt], ah, bl[p][q], bl[p][q + 1]);
        }
    }

    // ---- epilogue ----
    #pragma unroll
    for (int nt = 0; nt < 4; nt++) {
        const int r0 = row0 + wm + (lid >> 2);
        const int c  = col0 + wn + 8 * nt + 2 * (lid & 3);
        float2 s0 = {(t0[nt][0] + t1[nt][0]) * s, (t0[nt][1] + t1[nt][1]) * s};
        float2 s1 = {(t0[nt][2] + t1[nt][2]) * s, (t0[nt][3] + t1[nt][3]) * s};
        *(float2*)&out[(size_t)r0 * NDIM + c]       = s0;
        *(float2*)&out[(size_t)(r0 + 8) * NDIM + c] = s1;
    }
}

extern "C" void kernel_launch(void* const* d_in, const int* in_sizes, int n_in,
                              void* d_out, int out_size) {
    // metadata order: x, adj (UNUSED), W, att (UNUSED), self_weight
    const float* x  = (const float*)d_in[0];
    const float* W  = (const float*)d_in[2];
    const float* sw = (const float*)d_in[4];
    float* out      = (float*)d_out;

    cudaFuncSetAttribute(gat_hmma_kernel,
                         cudaFuncAttributeMaxDynamicSharedMemorySize, SMEM_TOTAL);

    prep_kernel<<<1040, 256>>>(x, W);
    dim3 grid((MDIM / TM) * (NDIM / TN));         // 128 * 2 = 256 blocks
    gat_hmma_kernel<<<grid, 256, SMEM_TOTAL>>>(sw, out);
}